// round 3
// baseline (speedup 1.0000x reference)
#include <cuda_runtime.h>
#include <cuda_bf16.h>

#define NN_   8192
#define CC_   256
#define EE_   262144
#define HH_   4
#define DH_   64

typedef unsigned long long ull;

// ---------------- packed f32x2 helpers (sm_103a) ----------------
__device__ __forceinline__ ull ffma2(ull a, ull b, ull c) {
    ull d;
    asm("fma.rn.f32x2 %0, %1, %2, %3;" : "=l"(d) : "l"(a), "l"(b), "l"(c));
    return d;
}
__device__ __forceinline__ ull fmul2(ull a, ull b) {
    ull d;
    asm("mul.rn.f32x2 %0, %1, %2;" : "=l"(d) : "l"(a), "l"(b));
    return d;
}
__device__ __forceinline__ ull fadd2(ull a, ull b) {
    ull d;
    asm("add.rn.f32x2 %0, %1, %2;" : "=l"(d) : "l"(a), "l"(b));
    return d;
}
__device__ __forceinline__ ull pack2(float x, float y) {
    ull r;
    asm("mov.b64 %0, {%1, %2};" : "=l"(r) : "f"(x), "f"(y));
    return r;
}
__device__ __forceinline__ float2 unpack2(ull v) {
    float2 r;
    asm("mov.b64 {%0, %1}, %2;" : "=f"(r.x), "=f"(r.y) : "l"(v));
    return r;
}

// ---------------- device scratch (no allocations allowed) ----------------
__device__ float g_deg[NN_];
__device__ float g_val[EE_];
__device__ float g_hi[NN_ * CC_];
__device__ float g_local[NN_ * CC_];
__device__ float g_qkv[NN_ * 3 * CC_];
__device__ float g_attn[NN_ * CC_];
__device__ float g_tmp[NN_ * CC_];
__device__ float g_glob[NN_ * CC_];
__device__ int   g_adj64;

// ---------------- adj dtype detection (int64 vs int32) -------------------
// Node ids are in [0, 8192). If the buffer is int64 (little endian), every
// odd 32-bit word is 0. If int32, odd words are random ids — P(all 256
// sampled odd words are 0) ~ (1/8192)^256 ~ 0. Parallel check: 256 threads,
// one odd word each, reduced with __syncthreads_count (no serial latency
// chain — the old single-thread loop cost ~150us of dependent DRAM loads).
__global__ void detect_adj_k(const int* __restrict__ w) {
    int nz = (w[2 * threadIdx.x + 1] != 0) ? 1 : 0;
    int cnt = __syncthreads_count(nz);
    if (threadIdx.x == 0) g_adj64 = (cnt == 0) ? 1 : 0;
}

__device__ __forceinline__ int adj_at(const void* adj, long long pos) {
    if (g_adj64) return (int)((const long long*)adj)[pos];
    return ((const int*)adj)[pos];
}

// ---------------- zero hi + deg ----------------
__global__ void zero_k() {
    int i = blockIdx.x * blockDim.x + threadIdx.x;
    float4 z = make_float4(0.f, 0.f, 0.f, 0.f);
    if (i < NN_ * CC_ / 4) reinterpret_cast<float4*>(g_hi)[i] = z;
    if (i < NN_ / 4)       reinterpret_cast<float4*>(g_deg)[i] = z;
}

// ---------------- degree (in-degree by col) ----------------
__global__ void deg_k(const void* adj) {
    int e = blockIdx.x * blockDim.x + threadIdx.x;
    if (e < EE_) {
        int c = adj_at(adj, (long long)EE_ + e);
        atomicAdd(&g_deg[c], 1.0f);
    }
}

// ---------------- edge normalization values ----------------
__global__ void val_k(const void* adj) {
    int e = blockIdx.x * blockDim.x + threadIdx.x;
    if (e >= EE_) return;
    int r = adj_at(adj, e);
    int c = adj_at(adj, (long long)EE_ + e);
    float p = g_deg[r] * g_deg[c];
    g_val[e] = (p > 0.f) ? rsqrtf(p) : 0.f;
}

// ---------------- GCN scatter: hi[col] += val * x[row] ----------------
// 64 consecutive threads handle one edge (one float4 channel-group each):
// adj/val loads broadcast within the warp, x[row] gathers and red.v4 into
// hi[col] are coalesced 1KB-contiguous accesses.
__global__ void scatter_k(const void* adj, const float* __restrict__ x) {
    long long i = (long long)blockIdx.x * blockDim.x + threadIdx.x;
    if (i >= (long long)EE_ * 64) return;
    int e  = (int)(i >> 6);
    int c4 = (int)(i & 63);
    float v = g_val[e];
    if (v == 0.f) return;
    int r = adj_at(adj, e);
    int c = adj_at(adj, (long long)EE_ + e);
    float4 xv = reinterpret_cast<const float4*>(x + (size_t)r * CC_)[c4];
    float* dst = g_hi + (size_t)c * CC_ + c4 * 4;
    asm volatile("red.global.add.v4.f32 [%0], {%1,%2,%3,%4};"
                 :: "l"(dst), "f"(v * xv.x), "f"(v * xv.y),
                    "f"(v * xv.z), "f"(v * xv.w)
                 : "memory");
}

// ---------------- generic SGEMM: C = op(A) * op(B) + bias + resid -----------
// BM=BN=64, BK=16, 256 threads, 4x4 micro-tile per thread, f32x2 packed FMAs.
// TRANSB=true : B is [N,K] row-major (C = A * B^T)
// TRANSB=false: B is [K,N] row-major (C = A * B)
// If A2 != null: A-tile is loaded as w*A + (1-w)*A2, w = sigmoid(alpha[0])
// (fuses the local/global blend into the final projection).
template <bool TRANSB>
__global__ void __launch_bounds__(256)
sgemm_k(const float* __restrict__ A, const float* __restrict__ A2,
        const float* __restrict__ alpha,
        const float* __restrict__ B,
        const float* __restrict__ bias, const float* __restrict__ resid,
        float* __restrict__ C, int M, int Nn, int K)
{
    __shared__ __align__(16) float As[16][68];
    __shared__ __align__(16) float Bs[16][68];
    int tid = threadIdx.x;
    int tx = tid & 15, ty = tid >> 4;
    int m0 = blockIdx.y * 64, n0 = blockIdx.x * 64;

    float w = 1.f, w2 = 0.f;
    if (A2) {
        w  = 1.f / (1.f + __expf(-alpha[0]));
        w2 = 1.f - w;
    }

    ull acc[4][2];
    #pragma unroll
    for (int i = 0; i < 4; i++) { acc[i][0] = 0ull; acc[i][1] = 0ull; }

    for (int k0 = 0; k0 < K; k0 += 16) {
        {   // A tile 64x16, store transposed As[k][m]
            int mr = tid >> 2;
            int kc = (tid & 3) * 4;
            size_t off = (size_t)(m0 + mr) * K + k0 + kc;
            float4 a = *reinterpret_cast<const float4*>(A + off);
            if (A2) {
                float4 a2 = *reinterpret_cast<const float4*>(A2 + off);
                a.x = w * a.x + w2 * a2.x;
                a.y = w * a.y + w2 * a2.y;
                a.z = w * a.z + w2 * a2.z;
                a.w = w * a.w + w2 * a2.w;
            }
            As[kc + 0][mr] = a.x; As[kc + 1][mr] = a.y;
            As[kc + 2][mr] = a.z; As[kc + 3][mr] = a.w;
        }
        if (TRANSB) {
            int nr = tid >> 2;
            int kc = (tid & 3) * 4;
            float4 b = *reinterpret_cast<const float4*>(
                B + (size_t)(n0 + nr) * K + k0 + kc);
            Bs[kc + 0][nr] = b.x; Bs[kc + 1][nr] = b.y;
            Bs[kc + 2][nr] = b.z; Bs[kc + 3][nr] = b.w;
        } else {
            int kr = tid >> 4;
            int nc = (tid & 15) * 4;
            float4 b = *reinterpret_cast<const float4*>(
                B + (size_t)(k0 + kr) * Nn + n0 + nc);
            *reinterpret_cast<float4*>(&Bs[kr][nc]) = b;
        }
        __syncthreads();
        #pragma unroll
        for (int kk = 0; kk < 16; kk++) {
            float4 a = *reinterpret_cast<const float4*>(&As[kk][ty * 4]);
            ulonglong2 b2 = *reinterpret_cast<const ulonglong2*>(&Bs[kk][tx * 4]);
            float av[4] = {a.x, a.y, a.z, a.w};
            #pragma unroll
            for (int i = 0; i < 4; i++) {
                ull ai = pack2(av[i], av[i]);
                acc[i][0] = ffma2(ai, b2.x, acc[i][0]);
                acc[i][1] = ffma2(ai, b2.y, acc[i][1]);
            }
        }
        __syncthreads();
    }

    #pragma unroll
    for (int i = 0; i < 4; i++) {
        int m = m0 + ty * 4 + i;
        int n = n0 + tx * 4;
        float2 p0 = unpack2(acc[i][0]);
        float2 p1 = unpack2(acc[i][1]);
        float4 r = make_float4(p0.x, p0.y, p1.x, p1.y);
        if (bias) {
            float4 bb = *reinterpret_cast<const float4*>(bias + n);
            r.x += bb.x; r.y += bb.y; r.z += bb.z; r.w += bb.w;
        }
        if (resid) {
            float4 rr = *reinterpret_cast<const float4*>(
                resid + (size_t)m * Nn + n);
            r.x += rr.x; r.y += rr.y; r.z += rr.z; r.w += rr.w;
        }
        *reinterpret_cast<float4*>(C + (size_t)m * Nn + n) = r;
    }
}

// ---------------- flash attention (fp32x2 packed, online softmax) ----------
// 1 query row per thread; q[64] and o[64] live in registers as 32 packed
// f32x2 pairs each. 256 threads/CTA, grid (32, 4) = 128 CTAs = one full wave
// on 148 SMs. K/V tiles of 64 keys staged in smem, read via broadcast
// LDS.128 whose register quads are already in packed-pair layout (zero pack
// cost). Rescale branch fires only on a new running max (~ln(8192) ~ 10x
// per row over 8192 keys).
__global__ void __launch_bounds__(256, 1) flash_k() {
    int h   = blockIdx.y;
    int row = blockIdx.x * 256 + threadIdx.x;
    __shared__ __align__(16) float ks[64][64];
    __shared__ __align__(16) float vs[64][64];

    const float* qp = g_qkv + (size_t)row * 768 + h * 64;
    ull q2[32], o2[32];
    #pragma unroll
    for (int i = 0; i < 16; i++) {
        ulonglong2 t = reinterpret_cast<const ulonglong2*>(qp)[i];
        q2[2 * i] = t.x; q2[2 * i + 1] = t.y;
    }
    #pragma unroll
    for (int i = 0; i < 32; i++) o2[i] = 0ull;
    float m = -1e30f, l = 0.f;

    for (int t = 0; t < NN_ / 64; t++) {
        if (t) __syncthreads();
        for (int i = threadIdx.x; i < 64 * 16; i += 256) {
            int r = i >> 4, c = (i & 15) << 2;
            const float* base = g_qkv + (size_t)(t * 64 + r) * 768 + h * 64;
            *reinterpret_cast<float4*>(&ks[r][c]) =
                *reinterpret_cast<const float4*>(base + 256 + c);
            *reinterpret_cast<float4*>(&vs[r][c]) =
                *reinterpret_cast<const float4*>(base + 512 + c);
        }
        __syncthreads();
        #pragma unroll 1
        for (int j = 0; j < 64; j++) {
            const ulonglong2* kp = reinterpret_cast<const ulonglong2*>(&ks[j][0]);
            ull s0 = 0ull, s1 = 0ull, s2 = 0ull, s3 = 0ull;
            #pragma unroll
            for (int d8 = 0; d8 < 8; d8++) {
                ulonglong2 ka = kp[2 * d8];
                ulonglong2 kb = kp[2 * d8 + 1];
                s0 = ffma2(q2[4 * d8 + 0], ka.x, s0);
                s1 = ffma2(q2[4 * d8 + 1], ka.y, s1);
                s2 = ffma2(q2[4 * d8 + 2], kb.x, s2);
                s3 = ffma2(q2[4 * d8 + 3], kb.y, s3);
            }
            ull st = fadd2(fadd2(s0, s1), fadd2(s2, s3));
            float2 sp = unpack2(st);
            float s = (sp.x + sp.y) * 0.125f;
            float p;
            if (s > m) {
                float corr = __expf(m - s);
                l *= corr;
                ull cc = pack2(corr, corr);
                #pragma unroll
                for (int d = 0; d < 32; d++) o2[d] = fmul2(o2[d], cc);
                m = s; p = 1.f;
            } else {
                p = __expf(s - m);
            }
            l += p;
            ull pp = pack2(p, p);
            const ulonglong2* vp = reinterpret_cast<const ulonglong2*>(&vs[j][0]);
            #pragma unroll
            for (int d8 = 0; d8 < 8; d8++) {
                ulonglong2 va = vp[2 * d8];
                ulonglong2 vb = vp[2 * d8 + 1];
                o2[4 * d8 + 0] = ffma2(pp, va.x, o2[4 * d8 + 0]);
                o2[4 * d8 + 1] = ffma2(pp, va.y, o2[4 * d8 + 1]);
                o2[4 * d8 + 2] = ffma2(pp, vb.x, o2[4 * d8 + 2]);
                o2[4 * d8 + 3] = ffma2(pp, vb.y, o2[4 * d8 + 3]);
            }
        }
    }

    float inv = 1.f / l;
    ull iv = pack2(inv, inv);
    float* op = g_attn + (size_t)row * CC_ + h * 64;
    #pragma unroll
    for (int i = 0; i < 16; i++) {
        ulonglong2 t;
        t.x = fmul2(o2[2 * i], iv);
        t.y = fmul2(o2[2 * i + 1], iv);
        reinterpret_cast<ulonglong2*>(op)[i] = t;
    }
}

// ---------------- layernorm over rows of 256 ----------------
__global__ void ln_k(const float* __restrict__ in, const float* __restrict__ g,
                     const float* __restrict__ b, float* __restrict__ out) {
    int row  = blockIdx.x * 8 + (threadIdx.x >> 5);
    int lane = threadIdx.x & 31;
    const float4* p = reinterpret_cast<const float4*>(in + (size_t)row * CC_);
    float4 v0 = p[lane * 2], v1 = p[lane * 2 + 1];
    float s = v0.x + v0.y + v0.z + v0.w + v1.x + v1.y + v1.z + v1.w;
    float qq = v0.x*v0.x + v0.y*v0.y + v0.z*v0.z + v0.w*v0.w
             + v1.x*v1.x + v1.y*v1.y + v1.z*v1.z + v1.w*v1.w;
    #pragma unroll
    for (int ofs = 16; ofs; ofs >>= 1) {
        s  += __shfl_xor_sync(0xffffffffu, s,  ofs);
        qq += __shfl_xor_sync(0xffffffffu, qq, ofs);
    }
    float mu  = s * (1.f / 256.f);
    float var = qq * (1.f / 256.f) - mu * mu;
    float rs  = rsqrtf(var + 1e-5f);
    const float4* gp = reinterpret_cast<const float4*>(g);
    const float4* bp = reinterpret_cast<const float4*>(b);
    float4 g0 = gp[lane*2], g1 = gp[lane*2+1];
    float4 b0 = bp[lane*2], b1 = bp[lane*2+1];
    float4 o0, o1;
    o0.x = (v0.x - mu) * rs * g0.x + b0.x;
    o0.y = (v0.y - mu) * rs * g0.y + b0.y;
    o0.z = (v0.z - mu) * rs * g0.z + b0.z;
    o0.w = (v0.w - mu) * rs * g0.w + b0.w;
    o1.x = (v1.x - mu) * rs * g1.x + b1.x;
    o1.y = (v1.y - mu) * rs * g1.y + b1.y;
    o1.z = (v1.z - mu) * rs * g1.z + b1.z;
    o1.w = (v1.w - mu) * rs * g1.w + b1.w;
    float4* op = reinterpret_cast<float4*>(out + (size_t)row * CC_);
    op[lane * 2]     = o0;
    op[lane * 2 + 1] = o1;
}

// ---------------- launch ----------------
extern "C" void kernel_launch(void* const* d_in, const int* in_sizes, int n_in,
                              void* d_out, int out_size) {
    const float* x     = (const float*)d_in[0];
    const void*  adj   = d_in[1];
    const float* wloc  = (const float*)d_in[2];
    const float* ipw   = (const float*)d_in[3];
    const float* ipb   = (const float*)d_in[4];
    const float* opw   = (const float*)d_in[5];
    const float* opb   = (const float*)d_in[6];
    const float* lng   = (const float*)d_in[7];
    const float* lnb   = (const float*)d_in[8];
    const float* alpha = (const float*)d_in[9];
    const float* fcw   = (const float*)d_in[10];
    const float* fcb   = (const float*)d_in[11];
    float* out = (float*)d_out;

    float *hi_p, *local_p, *qkv_p, *attn_p, *tmp_p, *glob_p;
    cudaGetSymbolAddress((void**)&hi_p,    g_hi);
    cudaGetSymbolAddress((void**)&local_p, g_local);
    cudaGetSymbolAddress((void**)&qkv_p,   g_qkv);
    cudaGetSymbolAddress((void**)&attn_p,  g_attn);
    cudaGetSymbolAddress((void**)&tmp_p,   g_tmp);
    cudaGetSymbolAddress((void**)&glob_p,  g_glob);

    detect_adj_k<<<1, 256>>>((const int*)adj);
    zero_k<<<(NN_ * CC_ / 4 + 255) / 256, 256>>>();
    deg_k<<<EE_ / 256, 256>>>(adj);
    val_k<<<EE_ / 256, 256>>>(adj);
    scatter_k<<<(EE_ * 64) / 256, 256>>>(adj, x);

    // local = hi @ weight_local          (NN form)
    sgemm_k<false><<<dim3(CC_ / 64, NN_ / 64), 256>>>(
        hi_p, nullptr, nullptr, wloc, nullptr, nullptr, local_p, NN_, CC_, CC_);

    // qkv = x @ in_proj_w^T + in_proj_b  (NT form)
    sgemm_k<true><<<dim3(3 * CC_ / 64, NN_ / 64), 256>>>(
        x, nullptr, nullptr, ipw, ipb, nullptr, qkv_p, NN_, 3 * CC_, CC_);

    // attention
    flash_k<<<dim3(NN_ / 256, HH_), 256>>>();

    // tmp = attn @ out_proj_w^T + out_proj_b + x  (residual fused)
    sgemm_k<true><<<dim3(CC_ / 64, NN_ / 64), 256>>>(
        attn_p, nullptr, nullptr, opw, opb, x, tmp_p, NN_, CC_, CC_);

    // global = LN(tmp)
    ln_k<<<NN_ / 8, 256>>>(tmp_p, lng, lnb, glob_p);

    // out = (w*local + (1-w)*global) @ fc_w^T + fc_b   (blend fused into A)
    sgemm_k<true><<<dim3(CC_ / 64, NN_ / 64), 256>>>(
        local_p, glob_p, alpha, fcw, fcb, nullptr, out, NN_, CC_, CC_);
}